// round 16
// baseline (speedup 1.0000x reference)
#include <cuda_runtime.h>
#include <cuda_fp16.h>
#include <cstdint>

#define ODIM 1024
#define XSZ  4194304
#define WSZ  1048576
#define KOFF XSZ
#define VOFF (2*XSZ)
#define PPITCH 80           // proj smem pitch: 32 fp16 + 16B pad
#define APITCH 144          // attn smem pitch: 64 fp16 + 16B pad
#define PJ_SMEM 61440       // 3 stages x (A 10240 + B 10240)
#define AT_STG  18432       // attn per-stage: K 9216 + V 9216
#define AT_SMEM 56320       // 3*18432 + vm 3*256 + pad

__device__ __align__(16) __half g_x[3*XSZ];   // fp16 q,k,v inputs
__device__ __align__(16) __half g_w[3*WSZ];   // fp16 weights
__device__ __align__(16) __half g_p[3*XSZ];   // fp16 projections qw,kw,vw

// ---------------- helpers ----------------
__device__ __forceinline__ uint32_t smem_u32(const void* p) {
    uint32_t a;
    asm("{ .reg .u64 t; cvta.to.shared.u64 t, %1; cvt.u32.u64 %0, t; }" : "=r"(a) : "l"(p));
    return a;
}
__device__ __forceinline__ uint32_t packh2(float e0, float e1) {
    __half2 h = __floats2half2_rn(e0, e1);
    return *reinterpret_cast<uint32_t*>(&h);
}
__device__ __forceinline__ float ex2a(float x) {   // exp(s/8) == ex2(s*0.125*log2e)
    float r;
    asm("ex2.approx.f32 %0, %1;" : "=f"(r) : "f"(x));
    return r;
}
__device__ __forceinline__ void ldsm4(uint32_t* r, uint32_t a) {
    asm volatile("ldmatrix.sync.aligned.m8n8.x4.shared.b16 {%0,%1,%2,%3}, [%4];"
                 : "=r"(r[0]), "=r"(r[1]), "=r"(r[2]), "=r"(r[3]) : "r"(a));
}
__device__ __forceinline__ void ldsm4t(uint32_t* r, uint32_t a) {
    asm volatile("ldmatrix.sync.aligned.m8n8.x4.trans.shared.b16 {%0,%1,%2,%3}, [%4];"
                 : "=r"(r[0]), "=r"(r[1]), "=r"(r[2]), "=r"(r[3]) : "r"(a));
}
__device__ __forceinline__ void mma_f16(float* d, const uint32_t* a, uint32_t b0, uint32_t b1) {
    asm volatile("mma.sync.aligned.m16n8k16.row.col.f32.f16.f16.f32 "
                 "{%0,%1,%2,%3}, {%4,%5,%6,%7}, {%8,%9}, {%0,%1,%2,%3};"
                 : "+f"(d[0]), "+f"(d[1]), "+f"(d[2]), "+f"(d[3])
                 : "r"(a[0]), "r"(a[1]), "r"(a[2]), "r"(a[3]), "r"(b0), "r"(b1));
}
#define CPA16(dst, src) asm volatile("cp.async.cg.shared.global [%0], [%1], 16;" :: "r"(dst), "l"(src) : "memory")
#define CPC()   asm volatile("cp.async.commit_group;" ::: "memory")
#define CPW(n)  asm volatile("cp.async.wait_group %0;" :: "n"(n) : "memory")

// ---------------- convert fp32 -> fp16 (3 tensors per launch) ----------------
__global__ void conv3(const float* __restrict__ s0, const float* __restrict__ s1,
                      const float* __restrict__ s2, __half* __restrict__ h, int n4each) {
    int i = blockIdx.x * blockDim.x + threadIdx.x;
    int a = i / n4each;
    if (a > 2) return;
    int j = i - a * n4each;
    const float* s = (a == 0) ? s0 : (a == 1) ? s1 : s2;
    float4 v = ((const float4*)s)[j];
    uint2 hh;
    hh.x = packh2(v.x, v.y);
    hh.y = packh2(v.z, v.w);
    ((uint2*)h)[(size_t)a * n4each + j] = hh;
}

// ---------------- projection (3 fused via grid.z): C=X@W^T, tile 128x128, BK=32, 3-stage ----------------
__global__ __launch_bounds__(256) void proj_mma(
    const __half* __restrict__ X_, const __half* __restrict__ W_, __half* __restrict__ P_)
{
    extern __shared__ __align__(16) char sm[];
    const uint32_t sb = smem_u32(sm);
    const int z = blockIdx.z;
    const __half* A_ = X_ + (size_t)z * XSZ;
    const __half* B_ = W_ + (size_t)z * WSZ;
    __half* C_ = P_ + (size_t)z * XSZ;
    const int tid = threadIdx.x, wr = tid >> 5, lane = tid & 31;
    const int n0 = blockIdx.x * 128, m0 = blockIdx.y * 128;
    const int g = lane >> 2, t = lane & 3;
    const int wm = wr >> 1, wn = wr & 1;
    const uint32_t rB  = ((lane >> 4) & 1) * 8 + (lane & 7);
    const uint32_t cBo = ((lane >> 3) & 1) * 16;
    float acc[2][8][4] = {};

    auto issue = [&](int kt) {
        if (kt < 32) {
            const uint32_t base = sb + (uint32_t)(kt % 3) * 20480;
            #pragma unroll
            for (int i = 0; i < 4; i++) {
                int idx = tid + 256 * i;
                int arr = idx >> 9, r = (idx >> 2) & 127, gc = idx & 3;
                size_t go = (size_t)((arr ? n0 : m0) + r) * ODIM + kt * 32 + gc * 8;
                CPA16(base + arr * 10240 + r * PPITCH + gc * 16, (arr ? B_ : A_) + go);
            }
        }
        CPC();
    };

    issue(0); issue(1);
    for (int kt = 0; kt < 32; kt++) {
        CPW(1);
        __syncthreads();
        issue(kt + 2);
        const uint32_t base = sb + (uint32_t)(kt % 3) * 20480;
        #pragma unroll
        for (int kc = 0; kc < 2; kc++) {
            uint32_t ah[2][4];
            #pragma unroll
            for (int mi = 0; mi < 2; mi++)
                ldsm4(ah[mi], base + (wm * 32 + mi * 16 + (lane & 15)) * PPITCH
                              + (lane >> 4) * 16 + kc * 32);
            #pragma unroll
            for (int nj = 0; nj < 4; nj++) {
                uint32_t bh[4];
                ldsm4(bh, base + 10240 + (wn * 64 + nj * 16 + rB) * PPITCH + cBo + kc * 32);
                #pragma unroll
                for (int mi = 0; mi < 2; mi++) {
                    mma_f16(acc[mi][2*nj],   ah[mi], bh[0], bh[1]);
                    mma_f16(acc[mi][2*nj+1], ah[mi], bh[2], bh[3]);
                }
            }
        }
    }
    #pragma unroll
    for (int mi = 0; mi < 2; mi++) {
        const int r0 = m0 + wm * 32 + mi * 16 + g, r1 = r0 + 8;
        #pragma unroll
        for (int nj = 0; nj < 8; nj++) {
            int col = n0 + wn * 64 + nj * 8 + 2 * t;
            *(uint32_t*)(C_ + (size_t)r0 * ODIM + col) = packh2(acc[mi][nj][0], acc[mi][nj][1]);
            *(uint32_t*)(C_ + (size_t)r1 * ODIM + col) = packh2(acc[mi][nj][2], acc[mi][nj][3]);
        }
    }
}

// ---------------- attention: 128 q-rows/CTA, 64-key tiles, 3-stage, causal skip ----------------
__global__ __launch_bounds__(256, 3) void attn_mma(
    const float* __restrict__ v_mask, const float* __restrict__ q_mask,
    float* __restrict__ out, const __half* __restrict__ P_)
{
    extern __shared__ __align__(16) char sm[];
    const uint32_t sb = smem_u32(sm);
    const int tid = threadIdx.x, wr = tid >> 5, lane = tid & 31;
    const int qt = blockIdx.x, h = blockIdx.y, b = blockIdx.z;
    const int q0 = qt * 128;
    const int g = lane >> 2, t = lane & 3;
    const uint32_t rB  = ((lane >> 4) & 1) * 8 + (lane & 7);
    const uint32_t cBo = ((lane >> 3) & 1) * 16;

    const __half* Q_b = P_ + (size_t)(b * 2048 + q0) * ODIM + h * 64;
    const __half* K_b = P_ + KOFF + (size_t)(b * 2048) * ODIM + h * 64;
    const __half* V_b = P_ + VOFF + (size_t)(b * 2048) * ODIM + h * 64;
    const float* vm = v_mask + (size_t)b * 2048;

    // ---- stage Q through stage-0 K area (two 64-row passes), grab fragments ----
    uint32_t qA[4][4];
    #pragma unroll
    for (int p = 0; p < 2; p++) {
        if (p) __syncthreads();
        #pragma unroll
        for (int i = 0; i < 2; i++) {
            int idx = tid + 256 * i;          // 512 = 64 rows x 8 chunks
            int r = (idx >> 3) & 63, gc = idx & 7;
            *(uint4*)(sm + r * APITCH + gc * 16) =
                *(const uint4*)(Q_b + (size_t)(p * 64 + r) * ODIM + gc * 8);
        }
        __syncthreads();
        if ((wr >> 2) == p) {
            const uint32_t aOff = sb + ((wr & 3) * 16 + (lane & 15)) * APITCH + (lane >> 4) * 16;
            #pragma unroll
            for (int kc = 0; kc < 4; kc++) ldsm4(qA[kc], aOff + kc * 32);
        }
    }
    __syncthreads();

    float oacc[8][4] = {};
    float lr0 = 0.f, lr1 = 0.f;
    const int qrow0 = q0 + wr * 16 + g;

    auto issue = [&](int kt2) {
        if (kt2 < 32) {
            const int st = kt2 % 3;
            const int k0 = kt2 * 64;
            const uint32_t bKs = sb + (uint32_t)st * AT_STG;
            #pragma unroll
            for (int i = 0; i < 4; i++) {
                int idx = tid + 256 * i;      // 1024 = 2 arrays x 64 rows x 8 chunks
                int arr = idx >> 9, r = (idx >> 3) & 63, gc = idx & 7;
                size_t go = (size_t)(k0 + r) * ODIM + gc * 8;
                CPA16(bKs + arr * 9216 + r * APITCH + gc * 16, (arr ? V_b : K_b) + go);
            }
            if (tid < 16) CPA16(sb + 3 * AT_STG + st * 256 + tid * 16, vm + k0 + tid * 4);
        }
        CPC();
    };

    const int start = 2 * qt;
    issue(start); issue(start + 1);
    for (int kt2 = start; kt2 < 32; kt2++) {
        const int st = kt2 % 3;
        const int k0 = kt2 * 64;
        CPW(1);
        __syncthreads();
        issue(kt2 + 2);
        const uint32_t bKs = sb + (uint32_t)st * AT_STG;
        const uint32_t bVs = bKs + 9216;
        const float* svm = (const float*)(sm + 3 * AT_STG + st * 256);
        const bool boundary = (kt2 < start + 2);   // only these tiles can hit kg<=qr

        #pragma unroll
        for (int jp = 0; jp < 4; jp++) {
            float s8[8] = {};
            #pragma unroll
            for (int kc = 0; kc < 4; kc++) {
                uint32_t bh[4];
                ldsm4(bh, bKs + (jp * 16 + rB) * APITCH + cBo + kc * 32);
                mma_f16(s8 + 0, qA[kc], bh[0], bh[1]);
                mma_f16(s8 + 4, qA[kc], bh[2], bh[3]);
            }
            float p[8];
            const int cb = jp * 16 + 2 * t;
            const float m0 = svm[cb], m1 = svm[cb + 1], m2 = svm[cb + 8], m3 = svm[cb + 9];
            if (boundary) {
                #pragma unroll
                for (int e = 0; e < 8; e++) {
                    int tile = e >> 2, c = e & 3;
                    int colL = cb + tile * 8 + (c & 1);
                    int kg = k0 + colL;
                    int qr = (c >= 2) ? qrow0 + 8 : qrow0;
                    float mv = (e < 4) ? ((e & 1) ? m1 : m0) : ((e & 1) ? m3 : m2);
                    p[e] = (kg <= qr) ? 0.f : ex2a(s8[e] * 0.18033688f) * mv;
                }
            } else {
                p[0] = ex2a(s8[0] * 0.18033688f) * m0;
                p[1] = ex2a(s8[1] * 0.18033688f) * m1;
                p[2] = ex2a(s8[2] * 0.18033688f) * m0;
                p[3] = ex2a(s8[3] * 0.18033688f) * m1;
                p[4] = ex2a(s8[4] * 0.18033688f) * m2;
                p[5] = ex2a(s8[5] * 0.18033688f) * m3;
                p[6] = ex2a(s8[6] * 0.18033688f) * m2;
                p[7] = ex2a(s8[7] * 0.18033688f) * m3;
            }
            lr0 += p[0] + p[1] + p[4] + p[5];
            lr1 += p[2] + p[3] + p[6] + p[7];
            uint32_t pa[4];
            pa[0] = packh2(p[0], p[1]);  pa[1] = packh2(p[2], p[3]);
            pa[2] = packh2(p[4], p[5]);  pa[3] = packh2(p[6], p[7]);
            #pragma unroll
            for (int j2 = 0; j2 < 4; j2++) {
                uint32_t vh[4];
                ldsm4t(vh, bVs + (jp * 16 + (lane & 15)) * APITCH + (j2 * 2 + (lane >> 4)) * 16);
                mma_f16(oacc[2*j2],   pa, vh[0], vh[1]);
                mma_f16(oacc[2*j2+1], pa, vh[2], vh[3]);
            }
        }
    }

    // ---- epilogue ----
    lr0 += __shfl_xor_sync(0xffffffffu, lr0, 1);
    lr0 += __shfl_xor_sync(0xffffffffu, lr0, 2);
    lr1 += __shfl_xor_sync(0xffffffffu, lr1, 1);
    lr1 += __shfl_xor_sync(0xffffffffu, lr1, 2);
    const float qm0 = q_mask[(size_t)b * 2048 + qrow0];
    const float qm1 = q_mask[(size_t)b * 2048 + qrow0 + 8];
    const float inv0 = (lr0 > 0.f) ? qm0 / lr0 : 0.f;
    const float inv1 = (lr1 > 0.f) ? qm1 / lr1 : 0.f;
    float* o0 = out + (size_t)(b * 2048 + qrow0) * ODIM + h * 64;
    float* o1 = o0 + (size_t)8 * ODIM;
    #pragma unroll
    for (int j = 0; j < 8; j++) {
        *(float2*)(o0 + j * 8 + 2 * t) = make_float2(oacc[j][0] * inv0, oacc[j][1] * inv0);
        *(float2*)(o1 + j * 8 + 2 * t) = make_float2(oacc[j][2] * inv1, oacc[j][3] * inv1);
    }
}

// ---------------- degenerate rows (q >= last valid key): exact tie-average, parallel ----------------
__global__ __launch_bounds__(512) void fallback_k(
    const float* __restrict__ v_mask, const float* __restrict__ q_mask,
    float* __restrict__ out, const __half* __restrict__ Vw)
{
    __shared__ int smax[512], scnt[512];
    __shared__ float spart[512];
    const int h = blockIdx.x, b = blockIdx.y, tid = threadIdx.x;
    const float* vm = v_mask + (size_t)b * 2048;

    int km = -1, c = 0;
    for (int k2 = tid; k2 < 2048; k2 += 512)
        if (vm[k2] != 0.f) { if (k2 > km) km = k2; c++; }
    smax[tid] = km; scnt[tid] = c;
    __syncthreads();
    for (int s = 256; s > 0; s >>= 1) {
        if (tid < s) {
            if (smax[tid + s] > smax[tid]) smax[tid] = smax[tid + s];
            scnt[tid] += scnt[tid + s];
        }
        __syncthreads();
    }
    const int kmax = (smax[0] < 0) ? 0 : smax[0];
    const int cnt = scnt[0];

    const int d = tid & 63, sl = tid >> 6;
    const __half* vh = Vw + (size_t)(b * 2048) * ODIM + h * 64 + d;
    float part = 0.f;
    for (int k2 = sl * 256; k2 < sl * 256 + 256; k2++)
        if (vm[k2] != 0.f) part += __half2float(vh[(size_t)k2 * ODIM]);
    spart[tid] = part;
    __syncthreads();

    if (tid < 64) {
        float tm = 0.f;
        #pragma unroll
        for (int s = 0; s < 8; s++) tm += spart[s * 64 + d];
        float suf = 0.f;
        for (int k2 = 2047; k2 >= kmax; k2--) {
            const float qm = q_mask[(size_t)b * 2048 + k2];
            const int den = cnt + (2047 - k2);
            out[((size_t)(b * 2048 + k2)) * ODIM + h * 64 + d] =
                (den > 0) ? qm * (tm + suf) / (float)den : 0.f;
            suf += __half2float(vh[(size_t)k2 * ODIM]);
        }
    }
}

// ---------------- launch ----------------
extern "C" void kernel_launch(void* const* d_in, const int* in_sizes, int n_in,
                              void* d_out, int out_size)
{
    const float* q     = (const float*)d_in[0];
    const float* k     = (const float*)d_in[1];
    const float* v     = (const float*)d_in[2];
    const float* vmask = (const float*)d_in[3];
    const float* qmask = (const float*)d_in[4];
    const float* Wq    = (const float*)d_in[5];
    const float* Wk    = (const float*)d_in[6];
    const float* Wv    = (const float*)d_in[7];
    float* out = (float*)d_out;

    __half *x16, *w16, *p16;
    cudaGetSymbolAddress((void**)&x16, g_x);
    cudaGetSymbolAddress((void**)&w16, g_w);
    cudaGetSymbolAddress((void**)&p16, g_p);

    cudaFuncSetAttribute(proj_mma, cudaFuncAttributeMaxDynamicSharedMemorySize, PJ_SMEM);
    cudaFuncSetAttribute(attn_mma, cudaFuncAttributeMaxDynamicSharedMemorySize, AT_SMEM);

    conv3<<<12288, 256>>>(q, k, v, x16, XSZ / 4);
    conv3<<<3072, 256>>>(Wq, Wk, Wv, w16, WSZ / 4);
    proj_mma<<<dim3(8, 32, 3), 256, PJ_SMEM>>>(x16, w16, p16);
    attn_mma<<<dim3(16, 16, 2), 256, AT_SMEM>>>(vmask, qmask, out, p16);
    fallback_k<<<dim3(16, 2), 512>>>(vmask, qmask, out, p16 + 2*XSZ);
}

// round 17
// speedup vs baseline: 1.4558x; 1.4558x over previous
#include <cuda_runtime.h>
#include <cuda_fp16.h>
#include <cstdint>

#define ODIM 1024
#define XSZ  4194304
#define WSZ  1048576
#define KOFF XSZ
#define VOFF (2*XSZ)
#define PPITCH 80           // proj smem pitch: 32 fp16 + 16B pad
#define APITCH 144          // attn smem pitch: 64 fp16 + 16B pad
#define PJ_SMEM 61440       // 3 stages x (A 10240 + B 10240)
#define AT_STG  18432       // attn per-stage: K 9216 + V 9216
#define AT_SMEM 55680       // 3*18432 + vm(fp16) 3*128
#define EC 0.1803368801f    // 0.125*log2(e)
#define EO 5.770780164f     // 4*log2(e): p = 2^(s*EC - EO) = exp(s/8 - 4)

__device__ __align__(16) __half g_x[3*XSZ];   // fp16 q,k,v inputs
__device__ __align__(16) __half g_w[3*WSZ];   // fp16 weights
__device__ __align__(16) __half g_p[3*XSZ];   // fp16 projections qw,kw,vw
__device__ __align__(16) __half g_vmh[2*2048];// v_mask as fp16

// ---------------- helpers ----------------
__device__ __forceinline__ uint32_t smem_u32(const void* p) {
    uint32_t a;
    asm("{ .reg .u64 t; cvta.to.shared.u64 t, %1; cvt.u32.u64 %0, t; }" : "=r"(a) : "l"(p));
    return a;
}
__device__ __forceinline__ uint32_t packh2(float e0, float e1) {
    __half2 h = __floats2half2_rn(e0, e1);
    return *reinterpret_cast<uint32_t*>(&h);
}
__device__ __forceinline__ float ex2a(float x) {
    float r;
    asm("ex2.approx.f32 %0, %1;" : "=f"(r) : "f"(x));
    return r;
}
__device__ __forceinline__ uint32_t h2ex2(uint32_t x) {
    uint32_t r;
    asm("ex2.approx.f16x2 %0, %1;" : "=r"(r) : "r"(x));
    return r;
}
__device__ __forceinline__ uint32_t h2mul(uint32_t a, uint32_t b) {
    __half2 r = __hmul2(*reinterpret_cast<__half2*>(&a), *reinterpret_cast<__half2*>(&b));
    return *reinterpret_cast<uint32_t*>(&r);
}
__device__ __forceinline__ uint32_t h2add(uint32_t a, uint32_t b) {
    __half2 r = __hadd2(*reinterpret_cast<__half2*>(&a), *reinterpret_cast<__half2*>(&b));
    return *reinterpret_cast<uint32_t*>(&r);
}
__device__ __forceinline__ void ldsm4(uint32_t* r, uint32_t a) {
    asm volatile("ldmatrix.sync.aligned.m8n8.x4.shared.b16 {%0,%1,%2,%3}, [%4];"
                 : "=r"(r[0]), "=r"(r[1]), "=r"(r[2]), "=r"(r[3]) : "r"(a));
}
__device__ __forceinline__ void ldsm4t(uint32_t* r, uint32_t a) {
    asm volatile("ldmatrix.sync.aligned.m8n8.x4.trans.shared.b16 {%0,%1,%2,%3}, [%4];"
                 : "=r"(r[0]), "=r"(r[1]), "=r"(r[2]), "=r"(r[3]) : "r"(a));
}
__device__ __forceinline__ void mma_f16(float* d, const uint32_t* a, uint32_t b0, uint32_t b1) {
    asm volatile("mma.sync.aligned.m16n8k16.row.col.f32.f16.f16.f32 "
                 "{%0,%1,%2,%3}, {%4,%5,%6,%7}, {%8,%9}, {%0,%1,%2,%3};"
                 : "+f"(d[0]), "+f"(d[1]), "+f"(d[2]), "+f"(d[3])
                 : "r"(a[0]), "r"(a[1]), "r"(a[2]), "r"(a[3]), "r"(b0), "r"(b1));
}
#define CPA16(dst, src) asm volatile("cp.async.cg.shared.global [%0], [%1], 16;" :: "r"(dst), "l"(src) : "memory")
#define CPC()   asm volatile("cp.async.commit_group;" ::: "memory")
#define CPW(n)  asm volatile("cp.async.wait_group %0;" :: "n"(n) : "memory")

// ---------------- convert fp32 -> fp16 (3 tensors; optional extra vmask tail) ----------------
__global__ void conv3(const float* __restrict__ s0, const float* __restrict__ s1,
                      const float* __restrict__ s2, __half* __restrict__ h, int n4each,
                      const float* __restrict__ vmsrc, __half* __restrict__ vmdst, int nvm4) {
    int i = blockIdx.x * blockDim.x + threadIdx.x;
    int a = i / n4each;
    if (a > 2) {
        int j = i - 3 * n4each;
        if (j < nvm4) {
            float4 v = ((const float4*)vmsrc)[j];
            uint2 hh;
            hh.x = packh2(v.x, v.y);
            hh.y = packh2(v.z, v.w);
            ((uint2*)vmdst)[j] = hh;
        }
        return;
    }
    int j = i - a * n4each;
    const float* s = (a == 0) ? s0 : (a == 1) ? s1 : s2;
    float4 v = ((const float4*)s)[j];
    uint2 hh;
    hh.x = packh2(v.x, v.y);
    hh.y = packh2(v.z, v.w);
    ((uint2*)h)[(size_t)a * n4each + j] = hh;
}

// ---------------- projection (3 fused via grid.z): C=X@W^T, tile 128x128, BK=32, 3-stage ----------------
__global__ __launch_bounds__(256) void proj_mma(
    const __half* __restrict__ X_, const __half* __restrict__ W_, __half* __restrict__ P_)
{
    extern __shared__ __align__(16) char sm[];
    const uint32_t sb = smem_u32(sm);
    const int z = blockIdx.z;
    const __half* A_ = X_ + (size_t)z * XSZ;
    const __half* B_ = W_ + (size_t)z * WSZ;
    __half* C_ = P_ + (size_t)z * XSZ;
    const int tid = threadIdx.x, wr = tid >> 5, lane = tid & 31;
    const int n0 = blockIdx.x * 128, m0 = blockIdx.y * 128;
    const int g = lane >> 2, t = lane & 3;
    const int wm = wr >> 1, wn = wr & 1;
    const uint32_t rB  = ((lane >> 4) & 1) * 8 + (lane & 7);
    const uint32_t cBo = ((lane >> 3) & 1) * 16;
    float acc[2][8][4] = {};

    auto issue = [&](int kt) {
        if (kt < 32) {
            const uint32_t base = sb + (uint32_t)(kt % 3) * 20480;
            #pragma unroll
            for (int i = 0; i < 4; i++) {
                int idx = tid + 256 * i;
                int arr = idx >> 9, r = (idx >> 2) & 127, gc = idx & 3;
                size_t go = (size_t)((arr ? n0 : m0) + r) * ODIM + kt * 32 + gc * 8;
                CPA16(base + arr * 10240 + r * PPITCH + gc * 16, (arr ? B_ : A_) + go);
            }
        }
        CPC();
    };

    issue(0); issue(1);
    for (int kt = 0; kt < 32; kt++) {
        CPW(1);
        __syncthreads();
        issue(kt + 2);
        const uint32_t base = sb + (uint32_t)(kt % 3) * 20480;
        #pragma unroll
        for (int kc = 0; kc < 2; kc++) {
            uint32_t ah[2][4];
            #pragma unroll
            for (int mi = 0; mi < 2; mi++)
                ldsm4(ah[mi], base + (wm * 32 + mi * 16 + (lane & 15)) * PPITCH
                              + (lane >> 4) * 16 + kc * 32);
            #pragma unroll
            for (int nj = 0; nj < 4; nj++) {
                uint32_t bh[4];
                ldsm4(bh, base + 10240 + (wn * 64 + nj * 16 + rB) * PPITCH + cBo + kc * 32);
                #pragma unroll
                for (int mi = 0; mi < 2; mi++) {
                    mma_f16(acc[mi][2*nj],   ah[mi], bh[0], bh[1]);
                    mma_f16(acc[mi][2*nj+1], ah[mi], bh[2], bh[3]);
                }
            }
        }
    }
    #pragma unroll
    for (int mi = 0; mi < 2; mi++) {
        const int r0 = m0 + wm * 32 + mi * 16 + g, r1 = r0 + 8;
        #pragma unroll
        for (int nj = 0; nj < 8; nj++) {
            int col = n0 + wn * 64 + nj * 8 + 2 * t;
            *(uint32_t*)(C_ + (size_t)r0 * ODIM + col) = packh2(acc[mi][nj][0], acc[mi][nj][1]);
            *(uint32_t*)(C_ + (size_t)r1 * ODIM + col) = packh2(acc[mi][nj][2], acc[mi][nj][3]);
        }
    }
}

// ---------------- attention: 128 q-rows/CTA, 64-key tiles, 3-stage, causal skip ----------------
__global__ __launch_bounds__(256) void attn_mma(
    const float* __restrict__ v_mask, const float* __restrict__ q_mask,
    float* __restrict__ out, const __half* __restrict__ P_,
    const __half* __restrict__ vmh_)
{
    extern __shared__ __align__(16) char sm[];
    const uint32_t sb = smem_u32(sm);
    const int tid = threadIdx.x, wr = tid >> 5, lane = tid & 31;
    const int qt = blockIdx.x, h = blockIdx.y, b = blockIdx.z;
    const int q0 = qt * 128;
    const int g = lane >> 2, t = lane & 3;
    const uint32_t rB  = ((lane >> 4) & 1) * 8 + (lane & 7);
    const uint32_t cBo = ((lane >> 3) & 1) * 16;

    const __half* Q_b = P_ + (size_t)(b * 2048 + q0) * ODIM + h * 64;
    const __half* K_b = P_ + KOFF + (size_t)(b * 2048) * ODIM + h * 64;
    const __half* V_b = P_ + VOFF + (size_t)(b * 2048) * ODIM + h * 64;
    const __half* vmh = vmh_ + (size_t)b * 2048;

    // ---- stage Q through stage-0 K area (two 64-row passes), grab fragments ----
    uint32_t qA[4][4];
    #pragma unroll
    for (int p = 0; p < 2; p++) {
        if (p) __syncthreads();
        #pragma unroll
        for (int i = 0; i < 2; i++) {
            int idx = tid + 256 * i;          // 512 = 64 rows x 8 chunks
            int r = (idx >> 3) & 63, gc = idx & 7;
            *(uint4*)(sm + r * APITCH + gc * 16) =
                *(const uint4*)(Q_b + (size_t)(p * 64 + r) * ODIM + gc * 8);
        }
        __syncthreads();
        if ((wr >> 2) == p) {
            const uint32_t aOff = sb + ((wr & 3) * 16 + (lane & 15)) * APITCH + (lane >> 4) * 16;
            #pragma unroll
            for (int kc = 0; kc < 4; kc++) ldsm4(qA[kc], aOff + kc * 32);
        }
    }
    __syncthreads();

    float oacc[8][4] = {};
    float lr0 = 0.f, lr1 = 0.f;
    const int qrow0 = q0 + wr * 16 + g;

    auto issue = [&](int kt2) {
        if (kt2 < 32) {
            const int st = kt2 % 3;
            const int k0 = kt2 * 64;
            const uint32_t bKs = sb + (uint32_t)st * AT_STG;
            #pragma unroll
            for (int i = 0; i < 4; i++) {
                int idx = tid + 256 * i;      // 1024 = 2 arrays x 64 rows x 8 chunks
                int arr = idx >> 9, r = (idx >> 3) & 63, gc = idx & 7;
                size_t go = (size_t)(k0 + r) * ODIM + gc * 8;
                CPA16(bKs + arr * 9216 + r * APITCH + gc * 16, (arr ? V_b : K_b) + go);
            }
            if (tid < 8) CPA16(sb + 3 * AT_STG + st * 128 + tid * 16, vmh + k0 + tid * 8);
        }
        CPC();
    };

    const int start = 2 * qt;
    issue(start); issue(start + 1);
    for (int kt2 = start; kt2 < 32; kt2++) {
        const int st = kt2 % 3;
        const int k0 = kt2 * 64;
        CPW(1);
        __syncthreads();
        issue(kt2 + 2);
        const uint32_t bKs = sb + (uint32_t)st * AT_STG;
        const uint32_t bVs = bKs + 9216;
        const __half* svmh = (const __half*)(sm + 3 * AT_STG + st * 128);
        const bool boundary = (kt2 < start + 2);   // only these tiles can hit kg<=qr

        #pragma unroll
        for (int jp = 0; jp < 4; jp++) {
            float s8[8] = {};
            #pragma unroll
            for (int kc = 0; kc < 4; kc++) {
                uint32_t bh[4];
                ldsm4(bh, bKs + (jp * 16 + rB) * APITCH + cBo + kc * 32);
                mma_f16(s8 + 0, qA[kc], bh[0], bh[1]);
                mma_f16(s8 + 4, qA[kc], bh[2], bh[3]);
            }
            const int cb = jp * 16 + 2 * t;
            uint32_t pa[4];
            if (boundary) {
                float p[8];
                #pragma unroll
                for (int e = 0; e < 8; e++) {
                    int tile = e >> 2, c = e & 3;
                    int colL = cb + tile * 8 + (c & 1);
                    int kg = k0 + colL;
                    int qr = (c >= 2) ? qrow0 + 8 : qrow0;
                    float mv = __half2float(svmh[colL]);
                    p[e] = (kg <= qr) ? 0.f : ex2a(fmaf(s8[e], EC, -EO)) * mv;
                }
                lr0 += p[0] + p[1] + p[4] + p[5];
                lr1 += p[2] + p[3] + p[6] + p[7];
                pa[0] = packh2(p[0], p[1]);  pa[1] = packh2(p[2], p[3]);
                pa[2] = packh2(p[4], p[5]);  pa[3] = packh2(p[6], p[7]);
            } else {
                const uint32_t vm01 = *(const uint32_t*)(svmh + cb);
                const uint32_t vm89 = *(const uint32_t*)(svmh + cb + 8);
                pa[0] = h2mul(h2ex2(packh2(fmaf(s8[0], EC, -EO), fmaf(s8[1], EC, -EO))), vm01);
                pa[1] = h2mul(h2ex2(packh2(fmaf(s8[2], EC, -EO), fmaf(s8[3], EC, -EO))), vm01);
                pa[2] = h2mul(h2ex2(packh2(fmaf(s8[4], EC, -EO), fmaf(s8[5], EC, -EO))), vm89);
                pa[3] = h2mul(h2ex2(packh2(fmaf(s8[6], EC, -EO), fmaf(s8[7], EC, -EO))), vm89);
                uint32_t su0 = h2add(pa[0], pa[2]);   // (p0+p4, p1+p5) -> lr0
                uint32_t su1 = h2add(pa[1], pa[3]);   // (p2+p6, p3+p7) -> lr1
                float2 f0 = __half22float2(*reinterpret_cast<__half2*>(&su0));
                float2 f1 = __half22float2(*reinterpret_cast<__half2*>(&su1));
                lr0 += f0.x + f0.y;
                lr1 += f1.x + f1.y;
            }
            #pragma unroll
            for (int j2 = 0; j2 < 4; j2++) {
                uint32_t vh[4];
                ldsm4t(vh, bVs + (jp * 16 + (lane & 15)) * APITCH + (j2 * 2 + (lane >> 4)) * 16);
                mma_f16(oacc[2*j2],   pa, vh[0], vh[1]);
                mma_f16(oacc[2*j2+1], pa, vh[2], vh[3]);
            }
        }
    }

    // ---- epilogue ----
    lr0 += __shfl_xor_sync(0xffffffffu, lr0, 1);
    lr0 += __shfl_xor_sync(0xffffffffu, lr0, 2);
    lr1 += __shfl_xor_sync(0xffffffffu, lr1, 1);
    lr1 += __shfl_xor_sync(0xffffffffu, lr1, 2);
    const float qm0 = q_mask[(size_t)b * 2048 + qrow0];
    const float qm1 = q_mask[(size_t)b * 2048 + qrow0 + 8];
    const float inv0 = (lr0 > 0.f) ? qm0 / lr0 : 0.f;
    const float inv1 = (lr1 > 0.f) ? qm1 / lr1 : 0.f;
    float* o0 = out + (size_t)(b * 2048 + qrow0) * ODIM + h * 64;
    float* o1 = o0 + (size_t)8 * ODIM;
    #pragma unroll
    for (int j = 0; j < 8; j++) {
        *(float2*)(o0 + j * 8 + 2 * t) = make_float2(oacc[j][0] * inv0, oacc[j][1] * inv0);
        *(float2*)(o1 + j * 8 + 2 * t) = make_float2(oacc[j][2] * inv1, oacc[j][3] * inv1);
    }
}

// ---------------- degenerate rows (q >= last valid key): exact tie-average, parallel ----------------
__global__ __launch_bounds__(512) void fallback_k(
    const float* __restrict__ v_mask, const float* __restrict__ q_mask,
    float* __restrict__ out, const __half* __restrict__ Vw)
{
    __shared__ int smax[512], scnt[512];
    __shared__ float spart[512];
    const int h = blockIdx.x, b = blockIdx.y, tid = threadIdx.x;
    const float* vm = v_mask + (size_t)b * 2048;

    int km = -1, c = 0;
    for (int k2 = tid; k2 < 2048; k2 += 512)
        if (vm[k2] != 0.f) { if (k2 > km) km = k2; c++; }
    smax[tid] = km; scnt[tid] = c;
    __syncthreads();
    for (int s = 256; s > 0; s >>= 1) {
        if (tid < s) {
            if (smax[tid + s] > smax[tid]) smax[tid] = smax[tid + s];
            scnt[tid] += scnt[tid + s];
        }
        __syncthreads();
    }
    const int kmax = (smax[0] < 0) ? 0 : smax[0];
    const int cnt = scnt[0];

    const int d = tid & 63, sl = tid >> 6;
    const __half* vh = Vw + (size_t)(b * 2048) * ODIM + h * 64 + d;
    float part = 0.f;
    for (int k2 = sl * 256; k2 < sl * 256 + 256; k2++)
        if (vm[k2] != 0.f) part += __half2float(vh[(size_t)k2 * ODIM]);
    spart[tid] = part;
    __syncthreads();

    if (tid < 64) {
        float tm = 0.f;
        #pragma unroll
        for (int s = 0; s < 8; s++) tm += spart[s * 64 + d];
        float suf = 0.f;
        for (int k2 = 2047; k2 >= kmax; k2--) {
            const float qm = q_mask[(size_t)b * 2048 + k2];
            const int den = cnt + (2047 - k2);
            out[((size_t)(b * 2048 + k2)) * ODIM + h * 64 + d] =
                (den > 0) ? qm * (tm + suf) / (float)den : 0.f;
            suf += __half2float(vh[(size_t)k2 * ODIM]);
        }
    }
}

// ---------------- launch ----------------
extern "C" void kernel_launch(void* const* d_in, const int* in_sizes, int n_in,
                              void* d_out, int out_size)
{
    const float* q     = (const float*)d_in[0];
    const float* k     = (const float*)d_in[1];
    const float* v     = (const float*)d_in[2];
    const float* vmask = (const float*)d_in[3];
    const float* qmask = (const float*)d_in[4];
    const float* Wq    = (const float*)d_in[5];
    const float* Wk    = (const float*)d_in[6];
    const float* Wv    = (const float*)d_in[7];
    float* out = (float*)d_out;

    __half *x16, *w16, *p16, *vmh;
    cudaGetSymbolAddress((void**)&x16, g_x);
    cudaGetSymbolAddress((void**)&w16, g_w);
    cudaGetSymbolAddress((void**)&p16, g_p);
    cudaGetSymbolAddress((void**)&vmh, g_vmh);

    cudaFuncSetAttribute(proj_mma, cudaFuncAttributeMaxDynamicSharedMemorySize, PJ_SMEM);
    cudaFuncSetAttribute(attn_mma, cudaFuncAttributeMaxDynamicSharedMemorySize, AT_SMEM);

    conv3<<<12288, 256>>>(q, k, v, x16, XSZ / 4, nullptr, nullptr, 0);
    conv3<<<3076, 256>>>(Wq, Wk, Wv, w16, WSZ / 4, vmask, vmh, 1024);
    proj_mma<<<dim3(8, 32, 3), 256, PJ_SMEM>>>(x16, w16, p16);
    attn_mma<<<dim3(16, 16, 2), 256, AT_SMEM>>>(vmask, qmask, out, p16, vmh);
    fallback_k<<<dim3(16, 2), 512>>>(vmask, qmask, out, p16 + 2*XSZ);
}